// round 15
// baseline (speedup 1.0000x reference)
#include <cuda_runtime.h>
#include <cuda_fp16.h>
#include <cstdint>

// Problem dims (fixed by the dataset)
#define B_ROWS 65536
#define F_DIM  256
#define U_DIM  1024

// GEMM tiling — R13 champion shape (at the sm_103a HMMA MAC-rate floor)
#define BM 128
#define BN 128
#define BK 64
#define KITERS (F_DIM / BK)       // 4
#define NTHREADS 256
#define STAGES 3

#define A_STG_BYTES 16384
#define STG_BYTES   32768
#define TBL_OFF     98304                      // wsq table after the 3 stages
#define SMEM_BYTES  (STAGES * STG_BYTES + 512) // 98816 -> still 2 CTAs/SM

#define MTILES (B_ROWS / BM)      // 512

// device-global scratch (allocations are forbidden)
__device__ __half g_xb[(size_t)B_ROWS * F_DIM];  // x in fp16 [B,F]
__device__ __half g_wt[(size_t)U_DIM * F_DIM];   // w transposed fp16 [U,F]
__device__ float g_wsq_part[8][U_DIM];           // per-f-chunk partial wsq
__device__ float g_xsq[B_ROWS];
__device__ int   g_claim[MTILES];                // producer election
__device__ int   g_done[MTILES];                 // m-tile conversion complete

// ---------------- PTX helpers ----------------
__device__ __forceinline__ uint32_t smem_u32(const void* p) {
    uint32_t a;
    asm("{ .reg .u64 t; cvta.to.shared.u64 t, %1; cvt.u32.u64 %0, t; }" : "=r"(a) : "l"(p));
    return a;
}
__device__ __forceinline__ void cp_async16(uint32_t dst, const void* src) {
    asm volatile("cp.async.cg.shared.global [%0], [%1], 16;" :: "r"(dst), "l"(src));
}
__device__ __forceinline__ void cp_commit() {
    asm volatile("cp.async.commit_group;" ::: "memory");
}
template<int N>
__device__ __forceinline__ void cp_wait() {
    asm volatile("cp.async.wait_group %0;" :: "n"(N) : "memory");
}
__device__ __forceinline__ void ldmatrix_x4(uint32_t* r, uint32_t addr) {
    asm volatile("ldmatrix.sync.aligned.m8n8.x4.shared.b16 {%0,%1,%2,%3}, [%4];"
                 : "=r"(r[0]), "=r"(r[1]), "=r"(r[2]), "=r"(r[3]) : "r"(addr));
}
__device__ __forceinline__ void mma_f16acc(uint32_t* c, const uint32_t* a,
                                           uint32_t b0, uint32_t b1) {
    asm volatile(
        "mma.sync.aligned.m16n8k16.row.col.f16.f16.f16.f16 "
        "{%0,%1}, {%2,%3,%4,%5}, {%6,%7}, {%0,%1};"
        : "+r"(c[0]), "+r"(c[1])
        : "r"(a[0]), "r"(a[1]), "r"(a[2]), "r"(a[3]), "r"(b0), "r"(b1));
}
__device__ __forceinline__ uint32_t pack_h16x2(float lo, float hi) {
    __half2 h = __floats2half2_rn(lo, hi);
    return *reinterpret_cast<uint32_t*>(&h);
}

// ---------------- w-prep: 256 blocks, one wave; also resets flags ----------------
__global__ void __launch_bounds__(256) wprep_kernel(const float* __restrict__ w) {
    if (blockIdx.x == 0) {                 // reset election flags for this call
        if (threadIdx.x < 256) {
            g_claim[threadIdx.x] = 0;       g_done[threadIdx.x] = 0;
            g_claim[threadIdx.x + 256] = 0; g_done[threadIdx.x + 256] = 0;
        }
    }
    __shared__ float t[32][33];
    __shared__ float red[8][32];
    int tx = threadIdx.x & 31, ty = threadIdx.x >> 5;
    int uo = ((int)blockIdx.x & 31) * 32;
    int fo = ((int)blockIdx.x >> 5) * 32;
    float acc = 0.0f;
    #pragma unroll
    for (int r = 0; r < 4; ++r) {
        int f = ty + 8 * r;
        float v = w[(size_t)(fo + f) * U_DIM + uo + tx];   // coalesced over tx
        t[f][tx] = v;
        acc += v * v;
    }
    __syncthreads();
    #pragma unroll
    for (int r = 0; r < 4; ++r) {
        int u = ty + 8 * r;
        g_wt[(size_t)(uo + u) * F_DIM + fo + tx] = __float2half(t[tx][u]);
    }
    red[ty][tx] = acc;
    __syncthreads();
    if (ty == 0) {
        float s = 0.0f;
        #pragma unroll
        for (int r = 0; r < 8; ++r) s += red[r][tx];
        g_wsq_part[fo >> 5][uo + tx] = s;
    }
}

// ---------------- main GEMM kernel (R13 body + producer election) ----------------
// out[m,n] = xsq[m] + wsq[n] - 2 * sum_k x[m,k]*wt[n,k]
// Preamble: one of the 8 CTAs per m-tile wins a CAS and converts that tile's
// 128 x-rows (fp32->fp16 + xsq); the rest acquire-spin on g_done. Prep traffic
// thus overlaps other CTAs' MMA work instead of running as a serial pre-pass.
__global__ void __launch_bounds__(NTHREADS, 2) rbf_gemm(float* __restrict__ out,
                                                        const float* __restrict__ x) {
    extern __shared__ char smem[];
    uint32_t sb = smem_u32(smem);

    int tid = threadIdx.x;
    int wid = tid >> 5, lid = tid & 31;
    int my = blockIdx.y;
    int m0 = my * BM;
    int n0 = blockIdx.x * BN;

    // ---- producer election + x-tile conversion ----
    __shared__ int s_winner;
    if (tid == 0) s_winner = (atomicCAS(&g_claim[my], 0, 1) == 0);
    __syncthreads();
    if (s_winner) {
        int half = lid >> 4;            // which of the warp's 2 rows
        int q = lid & 15;               // 16 lanes per row
        #pragma unroll 1
        for (int it = 0; it < 8; ++it) {
            int row = m0 + it * 16 + wid * 2 + half;
            const float4* xr = (const float4*)(x + (size_t)row * F_DIM);
            float4 v0 = xr[q * 4 + 0];
            float4 v1 = xr[q * 4 + 1];
            float4 v2 = xr[q * 4 + 2];
            float4 v3 = xr[q * 4 + 3];
            float s = v0.x * v0.x + v0.y * v0.y + v0.z * v0.z + v0.w * v0.w
                    + v1.x * v1.x + v1.y * v1.y + v1.z * v1.z + v1.w * v1.w
                    + v2.x * v2.x + v2.y * v2.y + v2.z * v2.z + v2.w * v2.w
                    + v3.x * v3.x + v3.y * v3.y + v3.z * v3.z + v3.w * v3.w;
            #pragma unroll
            for (int o = 8; o; o >>= 1) s += __shfl_xor_sync(0xffffffffu, s, o);
            if (q == 0) g_xsq[row] = s;
            uint4 p0, p1;
            p0.x = pack_h16x2(v0.x, v0.y);  p0.y = pack_h16x2(v0.z, v0.w);
            p0.z = pack_h16x2(v1.x, v1.y);  p0.w = pack_h16x2(v1.z, v1.w);
            p1.x = pack_h16x2(v2.x, v2.y);  p1.y = pack_h16x2(v2.z, v2.w);
            p1.z = pack_h16x2(v3.x, v3.y);  p1.w = pack_h16x2(v3.z, v3.w);
            uint4* dst = (uint4*)(g_xb + (size_t)row * F_DIM);
            dst[q * 2 + 0] = p0;
            dst[q * 2 + 1] = p1;
        }
        __syncthreads();
        __threadfence();
        if (tid == 0) atomicExch(&g_done[my], 1);
    } else {
        if (tid == 0) {
            int v;
            do {
                asm volatile("ld.global.acquire.gpu.b32 %0, [%1];"
                             : "=r"(v) : "l"(&g_done[my]) : "memory");
                if (!v) __nanosleep(64);
            } while (!v);
        }
        __syncthreads();
    }

    // ---- R13 GEMM body ----
    int g = lid >> 2, t = lid & 3;
    int wm = wid >> 2, wn = wid & 3;          // 2 x 4 warps; warp tile 64x32

    const __half* xa = g_xb + (size_t)m0 * F_DIM;
    const __half* wb = g_wt + (size_t)n0 * F_DIM;
    float* wsq_s = (float*)(smem + TBL_OFF);  // 128 floats

    if (tid < 128) {
        float s = 0.0f;
        #pragma unroll
        for (int p = 0; p < 8; ++p) s += g_wsq_part[p][n0 + tid];
        wsq_s[tid] = s;
    }

    uint32_t rowoffA[4], swzA[4];
    #pragma unroll
    for (int i = 0; i < 4; ++i) {
        int r = wm * 64 + i * 16 + (lid & 15);
        rowoffA[i] = (uint32_t)r * 128;
        swzA[i] = (uint32_t)(r & 7);
    }
    uint32_t rowoffB[2], swzB[2];
    #pragma unroll
    for (int jj = 0; jj < 2; ++jj) {
        int n = wn * 32 + jj * 16 + (lid & 7) + ((lid >> 4) << 3);
        rowoffB[jj] = A_STG_BYTES + (uint32_t)n * 128;
        swzB[jj] = (uint32_t)(n & 7);
    }
    uint32_t cA_lane = (uint32_t)(lid >> 4);
    uint32_t cB_lane = (uint32_t)((lid >> 3) & 1);

    uint32_t acc[2][4][4][2];
    #pragma unroll
    for (int bk = 0; bk < 2; ++bk)
        #pragma unroll
        for (int i = 0; i < 4; ++i)
            #pragma unroll
            for (int j = 0; j < 4; ++j) {
                acc[bk][i][j][0] = 0u;
                acc[bk][i][j][1] = 0u;
            }

    auto load_stage = [&](int stage, int kt) {
        uint32_t abase = sb + stage * STG_BYTES;
        #pragma unroll
        for (int r = 0; r < 4; ++r) {
            int chunk = tid + r * 256;
            int row = chunk >> 3, c = chunk & 7;
            cp_async16(abase + row * 128 + ((c ^ (row & 7)) << 4),
                       xa + (size_t)row * F_DIM + kt * BK + c * 8);
        }
        uint32_t bbase = abase + A_STG_BYTES;
        #pragma unroll
        for (int r = 0; r < 4; ++r) {
            int chunk = tid + r * 256;
            int row = chunk >> 3, c = chunk & 7;
            cp_async16(bbase + row * 128 + ((c ^ (row & 7)) << 4),
                       wb + (size_t)row * F_DIM + kt * BK + c * 8);
        }
        cp_commit();
    };

    load_stage(0, 0);
    load_stage(1, 1);
    load_stage(2, 2);

    #pragma unroll
    for (int kt = 0; kt < KITERS; ++kt) {
        int s = kt % STAGES;
        int bk = kt & 1;
        cp_wait<2>();
        __syncthreads();

        uint32_t a_base = sb + s * STG_BYTES;

        #pragma unroll
        for (int ks = 0; ks < 4; ++ks) {
            uint32_t a[4][4], b[2][4];
            uint32_t cA = 2 * ks + cA_lane;
            uint32_t cB = 2 * ks + cB_lane;
            #pragma unroll
            for (int i = 0; i < 4; ++i)
                ldmatrix_x4(a[i], a_base + rowoffA[i] + ((cA ^ swzA[i]) << 4));
            #pragma unroll
            for (int jj = 0; jj < 2; ++jj)
                ldmatrix_x4(b[jj], a_base + rowoffB[jj] + ((cB ^ swzB[jj]) << 4));
            #pragma unroll
            for (int i = 0; i < 4; ++i)
                #pragma unroll
                for (int jj = 0; jj < 2; ++jj) {
                    mma_f16acc(acc[bk][i][2 * jj + 0], a[i], b[jj][0], b[jj][1]);
                    mma_f16acc(acc[bk][i][2 * jj + 1], a[i], b[jj][2], b[jj][3]);
                }
        }
        __syncthreads();
        if (kt + STAGES < KITERS) load_stage(s, kt + STAGES);
        else cp_commit();  // empty group keeps wait<2> uniform
    }

    // fused epilogue: combine banks in fp32; out = xsq + wsq - 2*cross
    #pragma unroll
    for (int i = 0; i < 4; ++i) {
        int mlo = m0 + wm * 64 + i * 16 + g;
        int mhi = mlo + 8;
        float xlo = g_xsq[mlo];
        float xhi = g_xsq[mhi];
        #pragma unroll
        for (int j = 0; j < 4; ++j) {
            int nl = wn * 32 + j * 8 + 2 * t;
            float2 ws = *(const float2*)(wsq_s + nl);
            float2 p0 = __half22float2(*(__half2*)&acc[0][i][j][0]);
            float2 q0 = __half22float2(*(__half2*)&acc[1][i][j][0]);
            float2 p1 = __half22float2(*(__half2*)&acc[0][i][j][1]);
            float2 q1 = __half22float2(*(__half2*)&acc[1][i][j][1]);
            float2 olo, ohi;
            olo.x = fmaf(-2.0f, p0.x + q0.x, xlo + ws.x);
            olo.y = fmaf(-2.0f, p0.y + q0.y, xlo + ws.y);
            ohi.x = fmaf(-2.0f, p1.x + q1.x, xhi + ws.x);
            ohi.y = fmaf(-2.0f, p1.y + q1.y, xhi + ws.y);
            *(float2*)(out + (size_t)mlo * U_DIM + n0 + nl) = olo;
            *(float2*)(out + (size_t)mhi * U_DIM + n0 + nl) = ohi;
        }
    }
}

// ---------------- host launch ----------------
extern "C" void kernel_launch(void* const* d_in, const int* in_sizes, int n_in,
                              void* d_out, int out_size) {
    const float* x = (const float*)d_in[0];
    const float* w = (const float*)d_in[1];
    float* out = (float*)d_out;

    static int inited = 0;
    if (!inited) {
        cudaFuncSetAttribute(rbf_gemm, cudaFuncAttributeMaxDynamicSharedMemorySize,
                             SMEM_BYTES);
        inited = 1;
    }

    wprep_kernel<<<256, 256>>>(w);   // w transpose + wsq partials + flag reset

    dim3 grid(U_DIM / BN, B_ROWS / BM);  // (8, 512): n fastest -> x reuse in L2
    rbf_gemm<<<grid, NTHREADS, SMEM_BYTES>>>(out, x);
}

// round 16
// speedup vs baseline: 1.8587x; 1.8587x over previous
#include <cuda_runtime.h>
#include <cuda_fp16.h>
#include <cstdint>

// Problem dims (fixed by the dataset)
#define B_ROWS 65536
#define F_DIM  256
#define U_DIM  1024

// GEMM tiling — R13 champion (at the sm_103a HMMA MAC-rate floor)
#define BM 128
#define BN 128
#define BK 64                     // 64 fp16 = 128B row (swizzle atom)
#define KITERS (F_DIM / BK)       // 4
#define NTHREADS 256
#define STAGES 3

#define A_STG_BYTES 16384                    // 128*64*2
#define STG_BYTES   32768                    // A + B
#define SMEM_BYTES  (STAGES * STG_BYTES)     // 96KB -> 2 CTAs/SM

// device-global scratch (allocations are forbidden)
__device__ __half g_xb[(size_t)B_ROWS * F_DIM];  // x in fp16 [B,F]
__device__ __half g_wt[(size_t)U_DIM * F_DIM];   // w transposed fp16 [U,F]
__device__ float g_wsq[U_DIM];
__device__ float g_xsq[B_ROWS];

// ---------------- PTX helpers ----------------
__device__ __forceinline__ uint32_t smem_u32(const void* p) {
    uint32_t a;
    asm("{ .reg .u64 t; cvta.to.shared.u64 t, %1; cvt.u32.u64 %0, t; }" : "=r"(a) : "l"(p));
    return a;
}
__device__ __forceinline__ void cp_async16(uint32_t dst, const void* src) {
    asm volatile("cp.async.cg.shared.global [%0], [%1], 16;" :: "r"(dst), "l"(src));
}
__device__ __forceinline__ void cp_commit() {
    asm volatile("cp.async.commit_group;" ::: "memory");
}
template<int N>
__device__ __forceinline__ void cp_wait() {
    asm volatile("cp.async.wait_group %0;" :: "n"(N) : "memory");
}
__device__ __forceinline__ void ldmatrix_x4(uint32_t* r, uint32_t addr) {
    asm volatile("ldmatrix.sync.aligned.m8n8.x4.shared.b16 {%0,%1,%2,%3}, [%4];"
                 : "=r"(r[0]), "=r"(r[1]), "=r"(r[2]), "=r"(r[3]) : "r"(addr));
}
__device__ __forceinline__ void mma_f16acc(uint32_t* c, const uint32_t* a,
                                           uint32_t b0, uint32_t b1) {
    asm volatile(
        "mma.sync.aligned.m16n8k16.row.col.f16.f16.f16.f16 "
        "{%0,%1}, {%2,%3,%4,%5}, {%6,%7}, {%0,%1};"
        : "+r"(c[0]), "+r"(c[1])
        : "r"(a[0]), "r"(a[1]), "r"(a[2]), "r"(a[3]), "r"(b0), "r"(b1));
}
__device__ __forceinline__ uint32_t pack_h16x2(float lo, float hi) {
    __half2 h = __floats2half2_rn(lo, hi);
    return *reinterpret_cast<uint32_t*>(&h);
}

// ---------------- fused prologue ----------------
// Blocks [0, 32): w transpose + wsq — FIRST so they land in wave 1 and run
// concurrent with the x wave (proven in R13: saved ~4us vs trailing).
// Blocks [32, 32+XBLOCKS): x -> fp16 + xsq. 16 rows/block; each warp handles
// 2 rows with 16 lanes/row; 4 independent LDG.128 per thread.
// Single-use fp32 inputs are read with __ldcs (evict-first) so L2 stays
// available for g_xb/g_wt, which the GEMM streams next.
#define W_BLKS 32
#define ROWS_PER_BLK 16
#define XBLOCKS (B_ROWS / ROWS_PER_BLK)   // 4096
__global__ void __launch_bounds__(256) prep_kernel(const float* __restrict__ x,
                                                   const float* __restrict__ w) {
    int bid = blockIdx.x;
    if (bid >= W_BLKS) {
        int wid = threadIdx.x >> 5, lid = threadIdx.x & 31;
        int half = lid >> 4;            // which of the warp's 2 rows
        int q = lid & 15;               // 16 lanes per row
        int row = (bid - W_BLKS) * ROWS_PER_BLK + wid * 2 + half;

        const float4* xr = (const float4*)(x + (size_t)row * F_DIM);
        float4 v0 = __ldcs(xr + q * 4 + 0);   // 4 independent 16B loads
        float4 v1 = __ldcs(xr + q * 4 + 1);
        float4 v2 = __ldcs(xr + q * 4 + 2);
        float4 v3 = __ldcs(xr + q * 4 + 3);

        float s = v0.x * v0.x + v0.y * v0.y + v0.z * v0.z + v0.w * v0.w
                + v1.x * v1.x + v1.y * v1.y + v1.z * v1.z + v1.w * v1.w
                + v2.x * v2.x + v2.y * v2.y + v2.z * v2.z + v2.w * v2.w
                + v3.x * v3.x + v3.y * v3.y + v3.z * v3.z + v3.w * v3.w;
        #pragma unroll
        for (int o = 8; o; o >>= 1) s += __shfl_xor_sync(0xffffffffu, s, o);
        if (q == 0) g_xsq[row] = s;

        uint4 p0, p1;                   // 16 floats -> 8 f16x2 words -> 2x16B stores
        p0.x = pack_h16x2(v0.x, v0.y);  p0.y = pack_h16x2(v0.z, v0.w);
        p0.z = pack_h16x2(v1.x, v1.y);  p0.w = pack_h16x2(v1.z, v1.w);
        p1.x = pack_h16x2(v2.x, v2.y);  p1.y = pack_h16x2(v2.z, v2.w);
        p1.z = pack_h16x2(v3.x, v3.y);  p1.w = pack_h16x2(v3.z, v3.w);
        uint4* dst = (uint4*)(g_xb + (size_t)row * F_DIM);
        dst[q * 2 + 0] = p0;
        dst[q * 2 + 1] = p1;
    } else {
        __shared__ float t[32][33];
        __shared__ float red[8][32];
        int tx = threadIdx.x & 31, ty = threadIdx.x >> 5;
        int u0 = bid * 32;
        float acc = 0.0f;
        #pragma unroll 1
        for (int f0 = 0; f0 < F_DIM; f0 += 32) {
            __syncthreads();
            #pragma unroll
            for (int r = 0; r < 4; ++r) {
                int f = ty + 8 * r;
                float v = __ldcs(w + (size_t)(f0 + f) * U_DIM + u0 + tx);
                t[f][tx] = v;
                acc += v * v;
            }
            __syncthreads();
            #pragma unroll
            for (int r = 0; r < 4; ++r) {
                int u = ty + 8 * r;
                g_wt[(size_t)(u0 + u) * F_DIM + f0 + tx] = __float2half(t[tx][u]);
            }
        }
        red[ty][tx] = acc;
        __syncthreads();
        if (ty == 0) {
            float s = 0.0f;
            #pragma unroll
            for (int r = 0; r < 8; ++r) s += red[r][tx];
            g_wsq[u0 + tx] = s;
        }
    }
}

// ---------------- main GEMM kernel (byte-identical to R13 champion) ----------------
// out[m,n] = xsq[m] + wsq[n] - 2 * sum_k xb[m,k]*wt[n,k]
// fp16 accumulation in two banks (even/odd kt), combined in fp32 at epilogue.
// Swizzle: 128B rows of 8 16B-chunks; chunk c of row r at (c ^ (r&7)).
__global__ void __launch_bounds__(NTHREADS, 2) rbf_gemm(float* __restrict__ out) {
    extern __shared__ char smem[];
    uint32_t sb = smem_u32(smem);

    int tid = threadIdx.x;
    int wid = tid >> 5, lid = tid & 31;
    int g = lid >> 2, t = lid & 3;
    int wm = wid >> 2, wn = wid & 3;          // 2 x 4 warps; warp tile 64x32
    int m0 = blockIdx.y * BM;
    int n0 = blockIdx.x * BN;

    const __half* xa = g_xb + (size_t)m0 * F_DIM;
    const __half* wb = g_wt + (size_t)n0 * F_DIM;

    // ldmatrix per-lane bases (byte offsets within a stage)
    uint32_t rowoffA[4], swzA[4];
    #pragma unroll
    for (int i = 0; i < 4; ++i) {
        int r = wm * 64 + i * 16 + (lid & 15);
        rowoffA[i] = (uint32_t)r * 128;
        swzA[i] = (uint32_t)(r & 7);
    }
    uint32_t rowoffB[2], swzB[2];
    #pragma unroll
    for (int jj = 0; jj < 2; ++jj) {
        int n = wn * 32 + jj * 16 + (lid & 7) + ((lid >> 4) << 3);
        rowoffB[jj] = A_STG_BYTES + (uint32_t)n * 128;
        swzB[jj] = (uint32_t)(n & 7);
    }
    uint32_t cA_lane = (uint32_t)(lid >> 4);
    uint32_t cB_lane = (uint32_t)((lid >> 3) & 1);

    // two fp16 accumulator banks: [bank][i][j][2 regs]
    uint32_t acc[2][4][4][2];
    #pragma unroll
    for (int bk = 0; bk < 2; ++bk)
        #pragma unroll
        for (int i = 0; i < 4; ++i)
            #pragma unroll
            for (int j = 0; j < 4; ++j) {
                acc[bk][i][j][0] = 0u;
                acc[bk][i][j][1] = 0u;
            }

    // stage loader: A 1024 chunks + B 1024 chunks, 4 each per thread
    auto load_stage = [&](int stage, int kt) {
        uint32_t abase = sb + stage * STG_BYTES;
        #pragma unroll
        for (int r = 0; r < 4; ++r) {
            int chunk = tid + r * 256;
            int row = chunk >> 3, c = chunk & 7;
            cp_async16(abase + row * 128 + ((c ^ (row & 7)) << 4),
                       xa + (size_t)row * F_DIM + kt * BK + c * 8);
        }
        uint32_t bbase = abase + A_STG_BYTES;
        #pragma unroll
        for (int r = 0; r < 4; ++r) {
            int chunk = tid + r * 256;
            int row = chunk >> 3, c = chunk & 7;
            cp_async16(bbase + row * 128 + ((c ^ (row & 7)) << 4),
                       wb + (size_t)row * F_DIM + kt * BK + c * 8);
        }
        cp_commit();
    };

    load_stage(0, 0);
    load_stage(1, 1);
    load_stage(2, 2);

    #pragma unroll
    for (int kt = 0; kt < KITERS; ++kt) {
        int s = kt % STAGES;
        int bk = kt & 1;
        cp_wait<2>();
        __syncthreads();

        uint32_t a_base = sb + s * STG_BYTES;

        #pragma unroll
        for (int ks = 0; ks < 4; ++ks) {
            uint32_t a[4][4], b[2][4];
            uint32_t cA = 2 * ks + cA_lane;
            uint32_t cB = 2 * ks + cB_lane;
            #pragma unroll
            for (int i = 0; i < 4; ++i)
                ldmatrix_x4(a[i], a_base + rowoffA[i] + ((cA ^ swzA[i]) << 4));
            #pragma unroll
            for (int jj = 0; jj < 2; ++jj)
                ldmatrix_x4(b[jj], a_base + rowoffB[jj] + ((cB ^ swzB[jj]) << 4));
            #pragma unroll
            for (int i = 0; i < 4; ++i)
                #pragma unroll
                for (int jj = 0; jj < 2; ++jj) {
                    mma_f16acc(acc[bk][i][2 * jj + 0], a[i], b[jj][0], b[jj][1]);
                    mma_f16acc(acc[bk][i][2 * jj + 1], a[i], b[jj][2], b[jj][3]);
                }
        }
        __syncthreads();
        if (kt + STAGES < KITERS) load_stage(s, kt + STAGES);
        else cp_commit();  // empty group keeps wait<2> uniform
    }

    // fused epilogue: combine banks in fp32; out = xsq + wsq - 2*cross
    #pragma unroll
    for (int i = 0; i < 4; ++i) {
        int mlo = m0 + wm * 64 + i * 16 + g;
        int mhi = mlo + 8;
        float xlo = g_xsq[mlo];
        float xhi = g_xsq[mhi];
        #pragma unroll
        for (int j = 0; j < 4; ++j) {
            int n = n0 + wn * 32 + j * 8 + 2 * t;
            float2 ws = *(const float2*)(g_wsq + n);
            float2 p0 = __half22float2(*(__half2*)&acc[0][i][j][0]);
            float2 q0 = __half22float2(*(__half2*)&acc[1][i][j][0]);
            float2 p1 = __half22float2(*(__half2*)&acc[0][i][j][1]);
            float2 q1 = __half22float2(*(__half2*)&acc[1][i][j][1]);
            float2 olo, ohi;
            olo.x = fmaf(-2.0f, p0.x + q0.x, xlo + ws.x);
            olo.y = fmaf(-2.0f, p0.y + q0.y, xlo + ws.y);
            ohi.x = fmaf(-2.0f, p1.x + q1.x, xhi + ws.x);
            ohi.y = fmaf(-2.0f, p1.y + q1.y, xhi + ws.y);
            *(float2*)(out + (size_t)mlo * U_DIM + n) = olo;
            *(float2*)(out + (size_t)mhi * U_DIM + n) = ohi;
        }
    }
}

// ---------------- host launch ----------------
extern "C" void kernel_launch(void* const* d_in, const int* in_sizes, int n_in,
                              void* d_out, int out_size) {
    const float* x = (const float*)d_in[0];
    const float* w = (const float*)d_in[1];
    float* out = (float*)d_out;

    static int inited = 0;
    if (!inited) {
        cudaFuncSetAttribute(rbf_gemm, cudaFuncAttributeMaxDynamicSharedMemorySize,
                             SMEM_BYTES);
        inited = 1;
    }

    prep_kernel<<<W_BLKS + XBLOCKS, 256>>>(x, w);

    dim3 grid(U_DIM / BN, B_ROWS / BM);  // (8, 512): n-tiles adjacent -> A reuse in L2
    rbf_gemm<<<grid, NTHREADS, SMEM_BYTES>>>(out);
}